// round 9
// baseline (speedup 1.0000x reference)
#include <cuda_runtime.h>
#include <cuda_bf16.h>
#include <cuda_fp16.h>
#include <cstdint>

// ---------------------------------------------------------------------------
// ChunkedCrossAttention  (B=4, S=2048, D=1024, C=32, N=2, L=128, H=16, DK=64)
// Round 8: GEMM CTAs shrunk to 128 threads / 64x128 tiles (3-stage, swizzled)
// -> 3 CTAs/SM, 3 independent barrier domains (was 2x256thr/128x128 tiles).
// Per-warp tile shape unchanged (32x64) => identical numerics.
// Attention + pre-kernels unchanged from R7 (783us, rel_err 4.77e-4).
// ---------------------------------------------------------------------------

#define VALID_ROWS 1985

// ---------------- scratch ----------------
__device__ __nv_bfloat16 g_hsn_bf[4 * 2048 * 1024];
__device__ __nv_bfloat16 g_e_bf  [4 * 32 * 256 * 1024];
__device__ __nv_bfloat16 g_ao_bf [4 * 2048 * 1024];
__device__ __nv_bfloat16 g_wT_bf [4 * 1024 * 1024];
__device__ __half g_q_h[4 * 2048 * 1024];
__device__ __half g_k_h[4 * 32 * 256 * 1024];
__device__ __half g_v_h[4 * 32 * 256 * 1024];

// ---------------- helpers ----------------
__device__ __forceinline__ uint32_t smem_u32(const void* p) {
    uint32_t a;
    asm("{ .reg .u64 t; cvta.to.shared.u64 t, %1; cvt.u32.u64 %0, t; }" : "=r"(a) : "l"(p));
    return a;
}
#define CP_ASYNC16(dst, src) \
    asm volatile("cp.async.cg.shared.global [%0], [%1], 16;" :: "r"(dst), "l"(src) : "memory")
#define CP_COMMIT() asm volatile("cp.async.commit_group;" ::: "memory")
#define CP_WAIT(n)  asm volatile("cp.async.wait_group %0;" :: "n"(n) : "memory")

#define LDMATRIX_X4(r0, r1, r2, r3, addr) \
    asm volatile("ldmatrix.sync.aligned.m8n8.x4.shared.b16 {%0,%1,%2,%3}, [%4];" \
                 : "=r"(r0), "=r"(r1), "=r"(r2), "=r"(r3) : "r"(addr))
#define LDMATRIX_X4_TRANS(r0, r1, r2, r3, addr) \
    asm volatile("ldmatrix.sync.aligned.m8n8.x4.trans.shared.b16 {%0,%1,%2,%3}, [%4];" \
                 : "=r"(r0), "=r"(r1), "=r"(r2), "=r"(r3) : "r"(addr))

#define MMA_BF16(c, a, b0, b1) \
    asm volatile("mma.sync.aligned.m16n8k16.row.col.f32.bf16.bf16.f32 " \
                 "{%0,%1,%2,%3}, {%4,%5,%6,%7}, {%8,%9}, {%0,%1,%2,%3};" \
                 : "+f"((c)[0]), "+f"((c)[1]), "+f"((c)[2]), "+f"((c)[3]) \
                 : "r"((a)[0]), "r"((a)[1]), "r"((a)[2]), "r"((a)[3]), \
                   "r"(b0), "r"(b1))
#define MMA_F16(c, a, b0, b1) \
    asm volatile("mma.sync.aligned.m16n8k16.row.col.f32.f16.f16.f32 " \
                 "{%0,%1,%2,%3}, {%4,%5,%6,%7}, {%8,%9}, {%0,%1,%2,%3};" \
                 : "+f"((c)[0]), "+f"((c)[1]), "+f"((c)[2]), "+f"((c)[3]) \
                 : "r"((a)[0]), "r"((a)[1]), "r"((a)[2]), "r"((a)[3]), \
                   "r"(b0), "r"(b1))

__device__ __forceinline__ uint32_t pack_h2(float x, float y) {
    __half2 h = __floats2half2_rn(x, y);
    return *reinterpret_cast<uint32_t*>(&h);
}
// 2^y via range reduction + deg-4 Taylor (rel err ~4e-5, << fp16 rounding)
__device__ __forceinline__ float fexp2(float y) {
    y = fmaxf(y, -80.f);
    float r = rintf(y);
    float f = y - r;
    float p = 1.f + f * (0.693147182f + f * (0.240226512f +
              f * (0.0555041087f + f * 0.00961812911f)));
    return p * __int_as_float(((int)r + 127) << 23);
}

// ---------------------------------------------------------------------------
// 1. LayerNorm -> bf16 (rows t>=VALID zero-padded)
// ---------------------------------------------------------------------------
__global__ void ln_kernel(const float* __restrict__ h,
                          const float* __restrict__ gamma,
                          const float* __restrict__ beta) {
    const int m = blockIdx.x;
    const int b = m >> 11;
    const int t = m & 2047;
    const int tid = threadIdx.x;

    __nv_bfloat162* dst =
        reinterpret_cast<__nv_bfloat162*>(g_hsn_bf + (long)m * 1024 + tid * 4);
    if (t >= VALID_ROWS) {
        __nv_bfloat162 z = __floats2bfloat162_rn(0.f, 0.f);
        dst[0] = z; dst[1] = z;
        return;
    }
    const float4* src =
        reinterpret_cast<const float4*>(h + ((long)(b * 2048 + t + 63)) * 1024) + tid;
    float4 x = *src;

    float s = x.x + x.y + x.z + x.w;
    float q = x.x * x.x + x.y * x.y + x.z * x.z + x.w * x.w;
    #pragma unroll
    for (int o = 16; o > 0; o >>= 1) {
        s += __shfl_xor_sync(0xFFFFFFFFu, s, o);
        q += __shfl_xor_sync(0xFFFFFFFFu, q, o);
    }
    __shared__ float rs[8], rq[8];
    const int w = tid >> 5;
    if ((tid & 31) == 0) { rs[w] = s; rq[w] = q; }
    __syncthreads();
    s = 0.f; q = 0.f;
    #pragma unroll
    for (int i = 0; i < 8; i++) { s += rs[i]; q += rq[i]; }

    const float mu   = s * (1.0f / 1024.0f);
    const float var  = q * (1.0f / 1024.0f) - mu * mu;
    const float rstd = rsqrtf(var + 1e-5f);

    float4 g  = reinterpret_cast<const float4*>(gamma)[tid];
    float4 bb = reinterpret_cast<const float4*>(beta )[tid];
    float ox = (x.x - mu) * rstd * g.x + bb.x;
    float oy = (x.y - mu) * rstd * g.y + bb.y;
    float oz = (x.z - mu) * rstd * g.z + bb.z;
    float ow = (x.w - mu) * rstd * g.w + bb.w;
    dst[0] = __floats2bfloat162_rn(ox, oy);
    dst[1] = __floats2bfloat162_rn(oz, ow);
}

// ---------------------------------------------------------------------------
// 2. e -> bf16
// ---------------------------------------------------------------------------
__global__ void cvt_e(const float* __restrict__ src) {
    const long i = ((long)blockIdx.x * blockDim.x + threadIdx.x) * 8;
    float4 a = *reinterpret_cast<const float4*>(src + i);
    float4 b = *reinterpret_cast<const float4*>(src + i + 4);
    __nv_bfloat162 o[4];
    o[0] = __floats2bfloat162_rn(a.x, a.y);
    o[1] = __floats2bfloat162_rn(a.z, a.w);
    o[2] = __floats2bfloat162_rn(b.x, b.y);
    o[3] = __floats2bfloat162_rn(b.z, b.w);
    *reinterpret_cast<uint4*>(g_e_bf + i) = *reinterpret_cast<uint4*>(o);
}

// ---------------------------------------------------------------------------
// 3. Transposes (all 4 weights in one launch via blockIdx.z)
// ---------------------------------------------------------------------------
__global__ void transpose_w4(const float* __restrict__ s0, const float* __restrict__ s1,
                             const float* __restrict__ s2, const float* __restrict__ s3,
                             __nv_bfloat16* __restrict__ dbase) {
    const float* src = (blockIdx.z == 0) ? s0 : (blockIdx.z == 1) ? s1
                     : (blockIdx.z == 2) ? s2 : s3;
    __nv_bfloat16* dst = dbase + (long)blockIdx.z * 1024 * 1024;
    __shared__ float t[32][33];
    const int x  = blockIdx.x * 32 + threadIdx.x;
    const int y0 = blockIdx.y * 32 + threadIdx.y;
    #pragma unroll
    for (int i = 0; i < 4; i++)
        t[threadIdx.y + 8 * i][threadIdx.x] = src[(long)(y0 + 8 * i) * 1024 + x];
    __syncthreads();
    const int x2  = blockIdx.y * 32 + threadIdx.x;
    const int y20 = blockIdx.x * 32 + threadIdx.y;
    #pragma unroll
    for (int i = 0; i < 4; i++)
        dst[(long)(y20 + 8 * i) * 1024 + x2] =
            __float2bfloat16_rn(t[threadIdx.x][threadIdx.y + 8 * i]);
}

// ---------------------------------------------------------------------------
// 4. bf16 mma GEMM, 128 threads/CTA, 64x128 tile, XOR-swizzled 128B rows,
//    3-stage cp.async, 1 barrier/tile. 3 CTAs/SM.
//    HALFOUT: store __half (Q/K/V); else fp32 (+SHIFT epilogue).
// ---------------------------------------------------------------------------
#define ATILB  8192                    // 64 rows x 128 B
#define BTILB  16384                   // 128 rows x 128 B
#define ASTG   (ATILB + BTILB)         // 24576 B per stage
#define GM_SMEM (3 * ASTG)             // 73728 B -> 3 CTAs/SM

template <bool SHIFT, bool HALFOUT>
__global__ void __launch_bounds__(128)
mma_gemm(const __nv_bfloat16* __restrict__ A, const __nv_bfloat16* __restrict__ WT,
         const float* __restrict__ bias, const float* __restrict__ resid,
         void* __restrict__ Cout) {
    extern __shared__ char smemc[];
    const uint32_t sb = smem_u32(smemc);

    const int tid  = threadIdx.x;
    const int wid  = tid >> 5;
    const int lane = tid & 31;
    const int g    = lane >> 2;
    const int tig  = lane & 3;

    const int n0 = blockIdx.x * 128;
    const int m0 = blockIdx.y * 64;
    const int warp_m = (wid & 1) * 32;
    const int warp_n = (wid >> 1) * 64;

    // ---- A loader: thread -> row tid>>1 (0..63), 4 x 16B chunks (swizzled)
    const int larow = tid >> 1;
    const int lc0   = (tid & 1) * 4;
    const int am    = m0 + larow;
    bool avalid = true;
    const __nv_bfloat16* aptr;
    if (SHIFT) {
        avalid = (am & 2047) >= 63;
        aptr = avalid ? (A + (long)(am - 63) * 1024) : A;
    } else {
        aptr = A + (long)am * 1024;
    }
    uint32_t a_sw[4];
    #pragma unroll
    for (int i = 0; i < 4; i++)
        a_sw[i] = sb + (uint32_t)(larow * 128 + (((lc0 + i) ^ (larow & 7)) * 16));

    // ---- B loader: thread -> row tid (0..127), 8 x 16B chunks (swizzled)
    const __nv_bfloat16* bptr = WT + (long)(n0 + tid) * 1024;
    uint32_t b_sw[8];
    #pragma unroll
    for (int i = 0; i < 8; i++)
        b_sw[i] = sb + ATILB + (uint32_t)(tid * 128 + ((i ^ (tid & 7)) * 16));

    auto load_tile = [&](int kt, int st) {
        const uint32_t so = (uint32_t)st * ASTG;
        const __nv_bfloat16* ap = aptr + kt * 64 + lc0 * 8;
        const __nv_bfloat16* bp = bptr + kt * 64;
        if (avalid) {
            #pragma unroll
            for (int i = 0; i < 4; i++) CP_ASYNC16(a_sw[i] + so, ap + i * 8);
        } else {
            #pragma unroll
            for (int i = 0; i < 4; i++)
                *reinterpret_cast<uint4*>(smemc + (a_sw[i] - sb) + so) =
                    make_uint4(0, 0, 0, 0);
        }
        #pragma unroll
        for (int i = 0; i < 8; i++) CP_ASYNC16(b_sw[i] + so, bp + i * 8);
    };

    // ---- ldmatrix lane bases ----
    const int arow = warp_m + (lane & 15);
    const int axr  = arow & 7;
    const int ach  = (lane >> 4);
    const uint32_t abase = sb + (uint32_t)(arow * 128);
    const int brow = warp_n + (lane & 7) + ((lane >> 4) << 3);
    const int bxr  = brow & 7;
    const int bch  = ((lane >> 3) & 1);
    const uint32_t bbase = sb + ATILB + (uint32_t)(brow * 128);

    float c[2][8][4];
    #pragma unroll
    for (int mi = 0; mi < 2; mi++)
        #pragma unroll
        for (int ni = 0; ni < 8; ni++)
            #pragma unroll
            for (int r = 0; r < 4; r++) c[mi][ni][r] = 0.f;

    // prologue: stages 0,1 in flight
    load_tile(0, 0); CP_COMMIT();
    load_tile(1, 1); CP_COMMIT();

    int s_comp = 0, s_load = 2;
    #pragma unroll 1
    for (int kt = 0; kt < 16; kt++) {
        if (kt < 15) CP_WAIT(1); else CP_WAIT(0);
        __syncthreads();   // tile kt visible; stage s_load finished reading

        if (kt + 2 < 16) {
            load_tile(kt + 2, s_load);
            CP_COMMIT();
            s_load = (s_load == 2) ? 0 : s_load + 1;
        }

        const uint32_t so = (uint32_t)s_comp * ASTG;
        s_comp = (s_comp == 2) ? 0 : s_comp + 1;
        #pragma unroll
        for (int ks = 0; ks < 4; ks++) {
            const uint32_t aco = (uint32_t)(((ach + 2 * ks) ^ axr) * 16);
            const uint32_t bco = (uint32_t)(((bch + 2 * ks) ^ bxr) * 16);
            uint32_t a[2][4];
            #pragma unroll
            for (int mi = 0; mi < 2; mi++)
                LDMATRIX_X4(a[mi][0], a[mi][1], a[mi][2], a[mi][3],
                            abase + so + mi * (16 * 128) + aco);
            uint32_t b[4][4];
            #pragma unroll
            for (int nb = 0; nb < 4; nb++)
                LDMATRIX_X4(b[nb][0], b[nb][1], b[nb][2], b[nb][3],
                            bbase + so + nb * (16 * 128) + bco);
            #pragma unroll
            for (int mi = 0; mi < 2; mi++)
                #pragma unroll
                for (int nb = 0; nb < 4; nb++) {
                    MMA_BF16(c[mi][nb * 2 + 0], a[mi], b[nb][0], b[nb][1]);
                    MMA_BF16(c[mi][nb * 2 + 1], a[mi], b[nb][2], b[nb][3]);
                }
        }
    }

    // ---- epilogue ----
    #pragma unroll
    for (int mi = 0; mi < 2; mi++) {
        const int r0 = m0 + warp_m + mi * 16 + g;
        const int r1 = r0 + 8;
        #pragma unroll
        for (int ni = 0; ni < 8; ni++) {
            const int col = n0 + warp_n + ni * 8 + 2 * tig;
            float2 bs = *reinterpret_cast<const float2*>(bias + col);
            float2 o0 = make_float2(c[mi][ni][0] + bs.x, c[mi][ni][1] + bs.y);
            float2 o1 = make_float2(c[mi][ni][2] + bs.x, c[mi][ni][3] + bs.y);
            if (HALFOUT) {
                __half* Cm = (__half*)Cout;
                *reinterpret_cast<__half2*>(Cm + (long)r0 * 1024 + col) =
                    __floats2half2_rn(o0.x, o0.y);
                *reinterpret_cast<__half2*>(Cm + (long)r1 * 1024 + col) =
                    __floats2half2_rn(o1.x, o1.y);
            } else {
                float* Cm = (float*)Cout;
                if (SHIFT) {
                    float2 rv0 = *reinterpret_cast<const float2*>(resid + (long)r0 * 1024 + col);
                    float2 rv1 = *reinterpret_cast<const float2*>(resid + (long)r1 * 1024 + col);
                    if ((r0 & 2047) >= 63) { o0.x += rv0.x; o0.y += rv0.y; }
                    else o0 = rv0;
                    if ((r1 & 2047) >= 63) { o1.x += rv1.x; o1.y += rv1.y; }
                    else o1 = rv1;
                }
                *reinterpret_cast<float2*>(Cm + (long)r0 * 1024 + col) = o0;
                *reinterpret_cast<float2*>(Cm + (long)r1 * 1024 + col) = o1;
            }
        }
    }
}

// ---------------------------------------------------------------------------
// 5. Flash attention (unchanged from R5): block = (h, c, b), 128 threads.
// ---------------------------------------------------------------------------
#define AT_SMEM 82944

__global__ void __launch_bounds__(128) attn_kernel() {
    extern __shared__ char smc[];
    const uint32_t sb = smem_u32(smc);
    const uint32_t Qs = sb;
    const uint32_t Ks = sb + 64 * 144;
    const uint32_t Vs = Ks + 256 * 144;

    const int tid  = threadIdx.x;
    const int wid  = tid >> 5;
    const int lane = tid & 31;
    const int g    = lane >> 2;
    const int tig  = lane & 3;
    const int hh = blockIdx.x, cc = blockIdx.y, b = blockIdx.z;

    const __half* qg = g_q_h + ((long)(b * 2048 + cc * 64)) * 1024 + hh * 64;
    const long kvr = ((long)(b * 32 + cc)) * 256;
    const __half* kg = g_k_h + kvr * 1024 + hh * 64;
    const __half* vg = g_v_h + kvr * 1024 + hh * 64;

    {
        const int row = tid >> 1, hf = tid & 1;
        const uint32_t dst = Qs + row * 144 + hf * 64;
        const __half* src = qg + (long)row * 1024 + hf * 32;
        CP_ASYNC16(dst,      src);
        CP_ASYNC16(dst + 16, src + 8);
        CP_ASYNC16(dst + 32, src + 16);
        CP_ASYNC16(dst + 48, src + 24);
    }
    #pragma unroll
    for (int r = 0; r < 2; r++) {
        const int row = tid * 2 + r;
        const uint32_t dk = Ks + row * 144;
        const uint32_t dv = Vs + row * 144;
        const __half* sk = kg + (long)row * 1024;
        const __half* sv = vg + (long)row * 1024;
        #pragma unroll
        for (int i = 0; i < 8; i++) {
            CP_ASYNC16(dk + i * 16, sk + i * 8);
            CP_ASYNC16(dv + i * 16, sv + i * 8);
        }
    }
    CP_COMMIT();
    CP_WAIT(0);
    __syncthreads();

    float c[32][4];
    #pragma unroll
    for (int ni = 0; ni < 32; ni++)
        #pragma unroll
        for (int r = 0; r < 4; r++) c[ni][r] = 0.f;

    const uint32_t aaddr = Qs + (wid * 16 + (lane & 15)) * 144 + (lane >> 4) * 16;
    const uint32_t baddr = Ks + ((lane & 7) + ((lane >> 4) << 3)) * 144 + ((lane >> 3) & 1) * 16;

    #pragma unroll
    for (int ks = 0; ks < 4; ks++) {
        uint32_t a[4];
        LDMATRIX_X4(a[0], a[1], a[2], a[3], aaddr + ks * 32);
        #pragma unroll
        for (int jt = 0; jt < 16; jt++) {
            uint32_t bb[4];
            LDMATRIX_X4(bb[0], bb[1], bb[2], bb[3], baddr + jt * 2304 + ks * 32);
            MMA_F16(c[2 * jt],     a, bb[0], bb[1]);
            MMA_F16(c[2 * jt + 1], a, bb[2], bb[3]);
        }
    }

    float m0 = -1e30f, m1 = -1e30f;
    #pragma unroll
    for (int ni = 0; ni < 32; ni++) {
        m0 = fmaxf(m0, fmaxf(c[ni][0], c[ni][1]));
        m1 = fmaxf(m1, fmaxf(c[ni][2], c[ni][3]));
    }
    m0 = fmaxf(m0, __shfl_xor_sync(0xFFFFFFFFu, m0, 1));
    m0 = fmaxf(m0, __shfl_xor_sync(0xFFFFFFFFu, m0, 2));
    m1 = fmaxf(m1, __shfl_xor_sync(0xFFFFFFFFu, m1, 1));
    m1 = fmaxf(m1, __shfl_xor_sync(0xFFFFFFFFu, m1, 2));

    const float kk = 0.18033688011112042f;   // SCALE * log2(e)
    float s0 = 0.f, s1 = 0.f;
    #pragma unroll
    for (int ni = 0; ni < 32; ni++) {
        c[ni][0] = fexp2((c[ni][0] - m0) * kk); s0 += c[ni][0];
        c[ni][1] = fexp2((c[ni][1] - m0) * kk); s0 += c[ni][1];
        c[ni][2] = fexp2((c[ni][2] - m1) * kk); s1 += c[ni][2];
        c[ni][3] = fexp2((c[ni][3] - m1) * kk); s1 += c[ni][3];
    }
    s0 += __shfl_xor_sync(0xFFFFFFFFu, s0, 1);
    s0 += __shfl_xor_sync(0xFFFFFFFFu, s0, 2);
    s1 += __shfl_xor_sync(0xFFFFFFFFu, s1, 1);
    s1 += __shfl_xor_sync(0xFFFFFFFFu, s1, 2);
    const float inv0 = 1.f / s0, inv1 = 1.f / s1;

    uint32_t aP[16][4];
    #pragma unroll
    for (int kc = 0; kc < 16; kc++) {
        aP[kc][0] = pack_h2(c[2 * kc][0],     c[2 * kc][1]);
        aP[kc][1] = pack_h2(c[2 * kc][2],     c[2 * kc][3]);
        aP[kc][2] = pack_h2(c[2 * kc + 1][0], c[2 * kc + 1][1]);
        aP[kc][3] = pack_h2(c[2 * kc + 1][2], c[2 * kc + 1][3]);
    }

    float o[8][4];
    #pragma unroll
    for (int nt = 0; nt < 8; nt++)
        #pragma unroll
        for (int r = 0; r < 4; r++) o[nt][r] = 0.f;

    const uint32_t vaddr = Vs + (lane & 15) * 144 + (lane >> 4) * 16;
    #pragma unroll
    for (int kc = 0; kc < 16; kc++) {
        #pragma unroll
        for (int ngi = 0; ngi < 4; ngi++) {
            uint32_t bb[4];
            LDMATRIX_X4_TRANS(bb[0], bb[1], bb[2], bb[3],
                              vaddr + kc * 2304 + ngi * 32);
            MMA_F16(o[2 * ngi],     aP[kc], bb[0], bb[1]);
            MMA_F16(o[2 * ngi + 1], aP[kc], bb[2], bb[3]);
        }
    }

    __nv_bfloat16* og = g_ao_bf + ((long)(b * 2048 + cc * 64 + wid * 16)) * 1024 + hh * 64;
    #pragma unroll
    for (int nt = 0; nt < 8; nt++) {
        const int col = nt * 8 + tig * 2;
        *reinterpret_cast<__nv_bfloat162*>(og + (long)g * 1024 + col) =
            __floats2bfloat162_rn(o[nt][0] * inv0, o[nt][1] * inv0);
        *reinterpret_cast<__nv_bfloat162*>(og + (long)(g + 8) * 1024 + col) =
            __floats2bfloat162_rn(o[nt][2] * inv1, o[nt][3] * inv1);
    }
}

// ---------------------------------------------------------------------------
extern "C" void kernel_launch(void* const* d_in, const int* in_sizes, int n_in,
                              void* d_out, int out_size) {
    (void)in_sizes; (void)n_in; (void)out_size;
    const float* h     = (const float*)d_in[0];
    const float* e     = (const float*)d_in[1];
    const float* Wq    = (const float*)d_in[2];
    const float* bq    = (const float*)d_in[3];
    const float* Wk    = (const float*)d_in[4];
    const float* bk    = (const float*)d_in[5];
    const float* Wv    = (const float*)d_in[6];
    const float* bv    = (const float*)d_in[7];
    const float* Wo    = (const float*)d_in[8];
    const float* bo    = (const float*)d_in[9];
    const float* gamma = (const float*)d_in[10];
    const float* beta  = (const float*)d_in[11];
    float* out = (float*)d_out;

    void *p_hsn, *p_e, *p_ao, *p_wT, *p_q, *p_k, *p_v;
    cudaGetSymbolAddress(&p_hsn, g_hsn_bf);
    cudaGetSymbolAddress(&p_e,   g_e_bf);
    cudaGetSymbolAddress(&p_ao,  g_ao_bf);
    cudaGetSymbolAddress(&p_wT,  g_wT_bf);
    cudaGetSymbolAddress(&p_q,   g_q_h);
    cudaGetSymbolAddress(&p_k,   g_k_h);
    cudaGetSymbolAddress(&p_v,   g_v_h);
    __nv_bfloat16* wT = (__nv_bfloat16*)p_wT;
    __nv_bfloat16* wTq = wT;
    __nv_bfloat16* wTk = wT + 1024 * 1024;
    __nv_bfloat16* wTv = wT + 2 * 1024 * 1024;
    __nv_bfloat16* wTo = wT + 3 * 1024 * 1024;

    cudaFuncSetAttribute(attn_kernel, cudaFuncAttributeMaxDynamicSharedMemorySize,
                         AT_SMEM);
    cudaFuncSetAttribute(mma_gemm<false, true>,
                         cudaFuncAttributeMaxDynamicSharedMemorySize, GM_SMEM);
    cudaFuncSetAttribute(mma_gemm<false, false>,
                         cudaFuncAttributeMaxDynamicSharedMemorySize, GM_SMEM);
    cudaFuncSetAttribute(mma_gemm<true, false>,
                         cudaFuncAttributeMaxDynamicSharedMemorySize, GM_SMEM);

    // 1. LayerNorm -> bf16
    ln_kernel<<<4 * 2048, 256>>>(h, gamma, beta);
    // 2. e -> bf16
    cvt_e<<<16384, 256>>>(e);
    // 3. Weight transposes -> bf16 (single launch)
    transpose_w4<<<dim3(32, 32, 4), dim3(32, 8)>>>(Wq, Wk, Wv, Wo, wT);
    // 4-6. Projections (fp16 out)
    mma_gemm<false, true><<<dim3(8, 128), 128, GM_SMEM>>>(
        (const __nv_bfloat16*)p_hsn, wTq, bq, nullptr, p_q);
    mma_gemm<false, true><<<dim3(8, 512), 128, GM_SMEM>>>(
        (const __nv_bfloat16*)p_e, wTk, bk, nullptr, p_k);
    mma_gemm<false, true><<<dim3(8, 512), 128, GM_SMEM>>>(
        (const __nv_bfloat16*)p_e, wTv, bv, nullptr, p_v);
    // 7. Flash attention (fp16 tensor cores)
    attn_kernel<<<dim3(16, 32, 4), 128, AT_SMEM>>>();
    // 8. Output projection + shift + bias + residual
    mma_gemm<true, false><<<dim3(8, 128), 128, GM_SMEM>>>(
        (const __nv_bfloat16*)p_ao, wTo, bo, h, out);
}

// round 10
// speedup vs baseline: 1.5218x; 1.5218x over previous
#include <cuda_runtime.h>
#include <cuda_bf16.h>
#include <cuda_fp16.h>
#include <cstdint>

// ---------------------------------------------------------------------------
// ChunkedCrossAttention  (B=4, S=2048, D=1024, C=32, N=2, L=128, H=16, DK=64)
// Round 9: revert GEMM to R7 config (128x128 tile, 256 thr, 3-stage swizzled,
// 2 CTAs/SM — best known, 783us). New: Q+K+V projections merged into ONE
// launch (segmented grid) to recover launch-tail idle waves.
// R8's 64x128 tiles doubled B-traffic (L2 56%) and regressed; abandoned.
// ---------------------------------------------------------------------------

#define VALID_ROWS 1985

// ---------------- scratch ----------------
__device__ __nv_bfloat16 g_hsn_bf[4 * 2048 * 1024];
__device__ __nv_bfloat16 g_e_bf  [4 * 32 * 256 * 1024];
__device__ __nv_bfloat16 g_ao_bf [4 * 2048 * 1024];
__device__ __nv_bfloat16 g_wT_bf [4 * 1024 * 1024];
__device__ __half g_q_h[4 * 2048 * 1024];
__device__ __half g_k_h[4 * 32 * 256 * 1024];
__device__ __half g_v_h[4 * 32 * 256 * 1024];

// ---------------- helpers ----------------
__device__ __forceinline__ uint32_t smem_u32(const void* p) {
    uint32_t a;
    asm("{ .reg .u64 t; cvta.to.shared.u64 t, %1; cvt.u32.u64 %0, t; }" : "=r"(a) : "l"(p));
    return a;
}
#define CP_ASYNC16(dst, src) \
    asm volatile("cp.async.cg.shared.global [%0], [%1], 16;" :: "r"(dst), "l"(src) : "memory")
#define CP_COMMIT() asm volatile("cp.async.commit_group;" ::: "memory")
#define CP_WAIT(n)  asm volatile("cp.async.wait_group %0;" :: "n"(n) : "memory")

#define LDMATRIX_X4(r0, r1, r2, r3, addr) \
    asm volatile("ldmatrix.sync.aligned.m8n8.x4.shared.b16 {%0,%1,%2,%3}, [%4];" \
                 : "=r"(r0), "=r"(r1), "=r"(r2), "=r"(r3) : "r"(addr))
#define LDMATRIX_X4_TRANS(r0, r1, r2, r3, addr) \
    asm volatile("ldmatrix.sync.aligned.m8n8.x4.trans.shared.b16 {%0,%1,%2,%3}, [%4];" \
                 : "=r"(r0), "=r"(r1), "=r"(r2), "=r"(r3) : "r"(addr))

#define MMA_BF16(c, a, b0, b1) \
    asm volatile("mma.sync.aligned.m16n8k16.row.col.f32.bf16.bf16.f32 " \
                 "{%0,%1,%2,%3}, {%4,%5,%6,%7}, {%8,%9}, {%0,%1,%2,%3};" \
                 : "+f"((c)[0]), "+f"((c)[1]), "+f"((c)[2]), "+f"((c)[3]) \
                 : "r"((a)[0]), "r"((a)[1]), "r"((a)[2]), "r"((a)[3]), \
                   "r"(b0), "r"(b1))
#define MMA_F16(c, a, b0, b1) \
    asm volatile("mma.sync.aligned.m16n8k16.row.col.f32.f16.f16.f32 " \
                 "{%0,%1,%2,%3}, {%4,%5,%6,%7}, {%8,%9}, {%0,%1,%2,%3};" \
                 : "+f"((c)[0]), "+f"((c)[1]), "+f"((c)[2]), "+f"((c)[3]) \
                 : "r"((a)[0]), "r"((a)[1]), "r"((a)[2]), "r"((a)[3]), \
                   "r"(b0), "r"(b1))

__device__ __forceinline__ uint32_t pack_h2(float x, float y) {
    __half2 h = __floats2half2_rn(x, y);
    return *reinterpret_cast<uint32_t*>(&h);
}
// 2^y via range reduction + deg-4 Taylor (rel err ~4e-5, << fp16 rounding)
__device__ __forceinline__ float fexp2(float y) {
    y = fmaxf(y, -80.f);
    float r = rintf(y);
    float f = y - r;
    float p = 1.f + f * (0.693147182f + f * (0.240226512f +
              f * (0.0555041087f + f * 0.00961812911f)));
    return p * __int_as_float(((int)r + 127) << 23);
}

// ---------------------------------------------------------------------------
// 1. LayerNorm -> bf16 (rows t>=VALID zero-padded)
// ---------------------------------------------------------------------------
__global__ void ln_kernel(const float* __restrict__ h,
                          const float* __restrict__ gamma,
                          const float* __restrict__ beta) {
    const int m = blockIdx.x;
    const int b = m >> 11;
    const int t = m & 2047;
    const int tid = threadIdx.x;

    __nv_bfloat162* dst =
        reinterpret_cast<__nv_bfloat162*>(g_hsn_bf + (long)m * 1024 + tid * 4);
    if (t >= VALID_ROWS) {
        __nv_bfloat162 z = __floats2bfloat162_rn(0.f, 0.f);
        dst[0] = z; dst[1] = z;
        return;
    }
    const float4* src =
        reinterpret_cast<const float4*>(h + ((long)(b * 2048 + t + 63)) * 1024) + tid;
    float4 x = *src;

    float s = x.x + x.y + x.z + x.w;
    float q = x.x * x.x + x.y * x.y + x.z * x.z + x.w * x.w;
    #pragma unroll
    for (int o = 16; o > 0; o >>= 1) {
        s += __shfl_xor_sync(0xFFFFFFFFu, s, o);
        q += __shfl_xor_sync(0xFFFFFFFFu, q, o);
    }
    __shared__ float rs[8], rq[8];
    const int w = tid >> 5;
    if ((tid & 31) == 0) { rs[w] = s; rq[w] = q; }
    __syncthreads();
    s = 0.f; q = 0.f;
    #pragma unroll
    for (int i = 0; i < 8; i++) { s += rs[i]; q += rq[i]; }

    const float mu   = s * (1.0f / 1024.0f);
    const float var  = q * (1.0f / 1024.0f) - mu * mu;
    const float rstd = rsqrtf(var + 1e-5f);

    float4 g  = reinterpret_cast<const float4*>(gamma)[tid];
    float4 bb = reinterpret_cast<const float4*>(beta )[tid];
    float ox = (x.x - mu) * rstd * g.x + bb.x;
    float oy = (x.y - mu) * rstd * g.y + bb.y;
    float oz = (x.z - mu) * rstd * g.z + bb.z;
    float ow = (x.w - mu) * rstd * g.w + bb.w;
    dst[0] = __floats2bfloat162_rn(ox, oy);
    dst[1] = __floats2bfloat162_rn(oz, ow);
}

// ---------------------------------------------------------------------------
// 2. e -> bf16
// ---------------------------------------------------------------------------
__global__ void cvt_e(const float* __restrict__ src) {
    const long i = ((long)blockIdx.x * blockDim.x + threadIdx.x) * 8;
    float4 a = *reinterpret_cast<const float4*>(src + i);
    float4 b = *reinterpret_cast<const float4*>(src + i + 4);
    __nv_bfloat162 o[4];
    o[0] = __floats2bfloat162_rn(a.x, a.y);
    o[1] = __floats2bfloat162_rn(a.z, a.w);
    o[2] = __floats2bfloat162_rn(b.x, b.y);
    o[3] = __floats2bfloat162_rn(b.z, b.w);
    *reinterpret_cast<uint4*>(g_e_bf + i) = *reinterpret_cast<uint4*>(o);
}

// ---------------------------------------------------------------------------
// 3. Transposes (all 4 weights in one launch via blockIdx.z)
// ---------------------------------------------------------------------------
__global__ void transpose_w4(const float* __restrict__ s0, const float* __restrict__ s1,
                             const float* __restrict__ s2, const float* __restrict__ s3,
                             __nv_bfloat16* __restrict__ dbase) {
    const float* src = (blockIdx.z == 0) ? s0 : (blockIdx.z == 1) ? s1
                     : (blockIdx.z == 2) ? s2 : s3;
    __nv_bfloat16* dst = dbase + (long)blockIdx.z * 1024 * 1024;
    __shared__ float t[32][33];
    const int x  = blockIdx.x * 32 + threadIdx.x;
    const int y0 = blockIdx.y * 32 + threadIdx.y;
    #pragma unroll
    for (int i = 0; i < 4; i++)
        t[threadIdx.y + 8 * i][threadIdx.x] = src[(long)(y0 + 8 * i) * 1024 + x];
    __syncthreads();
    const int x2  = blockIdx.y * 32 + threadIdx.x;
    const int y20 = blockIdx.x * 32 + threadIdx.y;
    #pragma unroll
    for (int i = 0; i < 4; i++)
        dst[(long)(y20 + 8 * i) * 1024 + x2] =
            __float2bfloat16_rn(t[threadIdx.x][threadIdx.y + 8 * i]);
}

// ---------------------------------------------------------------------------
// 4. bf16 mma GEMM body (R7 config): 256 thr, 128x128 tile, XOR-swizzled
//    128B rows, 3-stage cp.async, 1 barrier/tile. 2 CTAs/SM.
// ---------------------------------------------------------------------------
#define TILEB  16384                   // 128 rows x 128 B
#define ASTG   (2 * TILEB)             // A + B per stage = 32768 B
#define GM_SMEM (3 * ASTG)             // 98304 B -> 2 CTAs/SM

template <bool SHIFT, bool HALFOUT>
__device__ __forceinline__ void
gemm_body(int m0, int n0,
          const __nv_bfloat16* __restrict__ A, const __nv_bfloat16* __restrict__ WT,
          const float* __restrict__ bias, const float* __restrict__ resid,
          void* __restrict__ Cout, char* smemc) {
    const uint32_t sb = smem_u32(smemc);
    const int tid  = threadIdx.x;
    const int wid  = tid >> 5;
    const int lane = tid & 31;
    const int g    = lane >> 2;
    const int tig  = lane & 3;
    const int warp_m = (wid & 3) * 32;
    const int warp_n = (wid >> 2) * 64;

    // ---- loader: thread -> row tid>>1, 4 x 16B chunks (swizzled) ----
    const int lrow = tid >> 1;
    const int lc0  = (tid & 1) * 4;
    const int lxr  = lrow & 7;
    const int am   = m0 + lrow;
    bool avalid = true;
    const __nv_bfloat16* aptr;
    if (SHIFT) {
        avalid = (am & 2047) >= 63;
        aptr = avalid ? (A + (long)(am - 63) * 1024) : A;
    } else {
        aptr = A + (long)am * 1024;
    }
    const __nv_bfloat16* bptr = WT + (long)(n0 + lrow) * 1024;
    uint32_t a_sw[4], b_sw[4];
    #pragma unroll
    for (int i = 0; i < 4; i++) {
        const uint32_t off = (uint32_t)(lrow * 128 + ((lc0 + i) ^ lxr) * 16);
        a_sw[i] = sb + off;
        b_sw[i] = sb + TILEB + off;
    }

    auto load_tile = [&](int kt, int st) {
        const uint32_t so = (uint32_t)st * ASTG;
        const __nv_bfloat16* ap = aptr + kt * 64 + lc0 * 8;
        const __nv_bfloat16* bp = bptr + kt * 64 + lc0 * 8;
        if (avalid) {
            #pragma unroll
            for (int i = 0; i < 4; i++) CP_ASYNC16(a_sw[i] + so, ap + i * 8);
        } else {
            #pragma unroll
            for (int i = 0; i < 4; i++)
                *reinterpret_cast<uint4*>(smemc + (a_sw[i] - sb) + so) =
                    make_uint4(0, 0, 0, 0);
        }
        #pragma unroll
        for (int i = 0; i < 4; i++) CP_ASYNC16(b_sw[i] + so, bp + i * 8);
    };

    // ---- ldmatrix lane bases ----
    const int arow = warp_m + (lane & 15);
    const int axr  = arow & 7;
    const int ach  = (lane >> 4);
    const uint32_t abase = sb + (uint32_t)(arow * 128);
    const int brow = warp_n + (lane & 7) + ((lane >> 4) << 3);
    const int bxr  = brow & 7;
    const int bch  = ((lane >> 3) & 1);
    const uint32_t bbase = sb + TILEB + (uint32_t)(brow * 128);

    float c[2][8][4];
    #pragma unroll
    for (int mi = 0; mi < 2; mi++)
        #pragma unroll
        for (int ni = 0; ni < 8; ni++)
            #pragma unroll
            for (int r = 0; r < 4; r++) c[mi][ni][r] = 0.f;

    load_tile(0, 0); CP_COMMIT();
    load_tile(1, 1); CP_COMMIT();

    int s_comp = 0, s_load = 2;
    #pragma unroll 1
    for (int kt = 0; kt < 16; kt++) {
        if (kt < 15) CP_WAIT(1); else CP_WAIT(0);
        __syncthreads();

        if (kt + 2 < 16) {
            load_tile(kt + 2, s_load);
            CP_COMMIT();
            s_load = (s_load == 2) ? 0 : s_load + 1;
        }

        const uint32_t so = (uint32_t)s_comp * ASTG;
        s_comp = (s_comp == 2) ? 0 : s_comp + 1;
        #pragma unroll
        for (int ks = 0; ks < 4; ks++) {
            const uint32_t aco = (uint32_t)(((ach + 2 * ks) ^ axr) * 16);
            const uint32_t bco = (uint32_t)(((bch + 2 * ks) ^ bxr) * 16);
            uint32_t a[2][4];
            #pragma unroll
            for (int mi = 0; mi < 2; mi++)
                LDMATRIX_X4(a[mi][0], a[mi][1], a[mi][2], a[mi][3],
                            abase + so + mi * (16 * 128) + aco);
            uint32_t b[4][4];
            #pragma unroll
            for (int nb = 0; nb < 4; nb++)
                LDMATRIX_X4(b[nb][0], b[nb][1], b[nb][2], b[nb][3],
                            bbase + so + nb * (16 * 128) + bco);
            #pragma unroll
            for (int mi = 0; mi < 2; mi++)
                #pragma unroll
                for (int nb = 0; nb < 4; nb++) {
                    MMA_BF16(c[mi][nb * 2 + 0], a[mi], b[nb][0], b[nb][1]);
                    MMA_BF16(c[mi][nb * 2 + 1], a[mi], b[nb][2], b[nb][3]);
                }
        }
    }

    // ---- epilogue ----
    #pragma unroll
    for (int mi = 0; mi < 2; mi++) {
        const int r0 = m0 + warp_m + mi * 16 + g;
        const int r1 = r0 + 8;
        #pragma unroll
        for (int ni = 0; ni < 8; ni++) {
            const int col = n0 + warp_n + ni * 8 + 2 * tig;
            float2 bs = *reinterpret_cast<const float2*>(bias + col);
            float2 o0 = make_float2(c[mi][ni][0] + bs.x, c[mi][ni][1] + bs.y);
            float2 o1 = make_float2(c[mi][ni][2] + bs.x, c[mi][ni][3] + bs.y);
            if (HALFOUT) {
                __half* Cm = (__half*)Cout;
                *reinterpret_cast<__half2*>(Cm + (long)r0 * 1024 + col) =
                    __floats2half2_rn(o0.x, o0.y);
                *reinterpret_cast<__half2*>(Cm + (long)r1 * 1024 + col) =
                    __floats2half2_rn(o1.x, o1.y);
            } else {
                float* Cm = (float*)Cout;
                if (SHIFT) {
                    float2 rv0 = *reinterpret_cast<const float2*>(resid + (long)r0 * 1024 + col);
                    float2 rv1 = *reinterpret_cast<const float2*>(resid + (long)r1 * 1024 + col);
                    if ((r0 & 2047) >= 63) { o0.x += rv0.x; o0.y += rv0.y; }
                    else o0 = rv0;
                    if ((r1 & 2047) >= 63) { o1.x += rv1.x; o1.y += rv1.y; }
                    else o1 = rv1;
                }
                *reinterpret_cast<float2*>(Cm + (long)r0 * 1024 + col) = o0;
                *reinterpret_cast<float2*>(Cm + (long)r1 * 1024 + col) = o1;
            }
        }
    }
}

// Merged Q+K+V launch: blockIdx.y in [0,64) Q | [64,320) K | [320,576) V.
__global__ void __launch_bounds__(256)
qkv_gemm(const __nv_bfloat16* __restrict__ Ahsn, const __nv_bfloat16* __restrict__ Ae,
         const __nv_bfloat16* __restrict__ wT,
         const float* __restrict__ bq, const float* __restrict__ bk,
         const float* __restrict__ bv,
         __half* __restrict__ q, __half* __restrict__ k, __half* __restrict__ v) {
    extern __shared__ char smemc[];
    const int y = blockIdx.y;
    const int n0 = blockIdx.x * 128;
    const __nv_bfloat16 *A, *WT;
    const float* bias;
    __half* out;
    int m0;
    if (y < 64)       { A = Ahsn; WT = wT;                 bias = bq; out = q; m0 = y * 128; }
    else if (y < 320) { A = Ae;   WT = wT + 1024 * 1024;   bias = bk; out = k; m0 = (y - 64) * 128; }
    else              { A = Ae;   WT = wT + 2 * 1024 * 1024; bias = bv; out = v; m0 = (y - 320) * 128; }
    gemm_body<false, true>(m0, n0, A, WT, bias, nullptr, out, smemc);
}

// O-projection (+shift/bias/residual), fp32 out.
__global__ void __launch_bounds__(256)
o_gemm(const __nv_bfloat16* __restrict__ A, const __nv_bfloat16* __restrict__ WT,
       const float* __restrict__ bias, const float* __restrict__ resid,
       float* __restrict__ Cout) {
    extern __shared__ char smemc[];
    gemm_body<true, false>(blockIdx.y * 128, blockIdx.x * 128, A, WT, bias, resid,
                           Cout, smemc);
}

// ---------------------------------------------------------------------------
// 5. Flash attention (unchanged from R5): block = (h, c, b), 128 threads.
// ---------------------------------------------------------------------------
#define AT_SMEM 82944

__global__ void __launch_bounds__(128) attn_kernel() {
    extern __shared__ char smc[];
    const uint32_t sb = smem_u32(smc);
    const uint32_t Qs = sb;
    const uint32_t Ks = sb + 64 * 144;
    const uint32_t Vs = Ks + 256 * 144;

    const int tid  = threadIdx.x;
    const int wid  = tid >> 5;
    const int lane = tid & 31;
    const int g    = lane >> 2;
    const int tig  = lane & 3;
    const int hh = blockIdx.x, cc = blockIdx.y, b = blockIdx.z;

    const __half* qg = g_q_h + ((long)(b * 2048 + cc * 64)) * 1024 + hh * 64;
    const long kvr = ((long)(b * 32 + cc)) * 256;
    const __half* kg = g_k_h + kvr * 1024 + hh * 64;
    const __half* vg = g_v_h + kvr * 1024 + hh * 64;

    {
        const int row = tid >> 1, hf = tid & 1;
        const uint32_t dst = Qs + row * 144 + hf * 64;
        const __half* src = qg + (long)row * 1024 + hf * 32;
        CP_ASYNC16(dst,      src);
        CP_ASYNC16(dst + 16, src + 8);
        CP_ASYNC16(dst + 32, src + 16);
        CP_ASYNC16(dst + 48, src + 24);
    }
    #pragma unroll
    for (int r = 0; r < 2; r++) {
        const int row = tid * 2 + r;
        const uint32_t dk = Ks + row * 144;
        const uint32_t dv = Vs + row * 144;
        const __half* sk = kg + (long)row * 1024;
        const __half* sv = vg + (long)row * 1024;
        #pragma unroll
        for (int i = 0; i < 8; i++) {
            CP_ASYNC16(dk + i * 16, sk + i * 8);
            CP_ASYNC16(dv + i * 16, sv + i * 8);
        }
    }
    CP_COMMIT();
    CP_WAIT(0);
    __syncthreads();

    float c[32][4];
    #pragma unroll
    for (int ni = 0; ni < 32; ni++)
        #pragma unroll
        for (int r = 0; r < 4; r++) c[ni][r] = 0.f;

    const uint32_t aaddr = Qs + (wid * 16 + (lane & 15)) * 144 + (lane >> 4) * 16;
    const uint32_t baddr = Ks + ((lane & 7) + ((lane >> 4) << 3)) * 144 + ((lane >> 3) & 1) * 16;

    #pragma unroll
    for (int ks = 0; ks < 4; ks++) {
        uint32_t a[4];
        LDMATRIX_X4(a[0], a[1], a[2], a[3], aaddr + ks * 32);
        #pragma unroll
        for (int jt = 0; jt < 16; jt++) {
            uint32_t bb[4];
            LDMATRIX_X4(bb[0], bb[1], bb[2], bb[3], baddr + jt * 2304 + ks * 32);
            MMA_F16(c[2 * jt],     a, bb[0], bb[1]);
            MMA_F16(c[2 * jt + 1], a, bb[2], bb[3]);
        }
    }

    float m0 = -1e30f, m1 = -1e30f;
    #pragma unroll
    for (int ni = 0; ni < 32; ni++) {
        m0 = fmaxf(m0, fmaxf(c[ni][0], c[ni][1]));
        m1 = fmaxf(m1, fmaxf(c[ni][2], c[ni][3]));
    }
    m0 = fmaxf(m0, __shfl_xor_sync(0xFFFFFFFFu, m0, 1));
    m0 = fmaxf(m0, __shfl_xor_sync(0xFFFFFFFFu, m0, 2));
    m1 = fmaxf(m1, __shfl_xor_sync(0xFFFFFFFFu, m1, 1));
    m1 = fmaxf(m1, __shfl_xor_sync(0xFFFFFFFFu, m1, 2));

    const float kk = 0.18033688011112042f;   // SCALE * log2(e)
    float s0 = 0.f, s1 = 0.f;
    #pragma unroll
    for (int ni = 0; ni < 32; ni++) {
        c[ni][0] = fexp2((c[ni][0] - m0) * kk); s0 += c[ni][0];
        c[ni][1] = fexp2((c[ni][1] - m0) * kk); s0 += c[ni][1];
        c[ni][2] = fexp2((c[ni][2] - m1) * kk); s1 += c[ni][2];
        c[ni][3] = fexp2((c[ni][3] - m1) * kk); s1 += c[ni][3];
    }
    s0 += __shfl_xor_sync(0xFFFFFFFFu, s0, 1);
    s0 += __shfl_xor_sync(0xFFFFFFFFu, s0, 2);
    s1 += __shfl_xor_sync(0xFFFFFFFFu, s1, 1);
    s1 += __shfl_xor_sync(0xFFFFFFFFu, s1, 2);
    const float inv0 = 1.f / s0, inv1 = 1.f / s1;

    uint32_t aP[16][4];
    #pragma unroll
    for (int kc = 0; kc < 16; kc++) {
        aP[kc][0] = pack_h2(c[2 * kc][0],     c[2 * kc][1]);
        aP[kc][1] = pack_h2(c[2 * kc][2],     c[2 * kc][3]);
        aP[kc][2] = pack_h2(c[2 * kc + 1][0], c[2 * kc + 1][1]);
        aP[kc][3] = pack_h2(c[2 * kc + 1][2], c[2 * kc + 1][3]);
    }

    float o[8][4];
    #pragma unroll
    for (int nt = 0; nt < 8; nt++)
        #pragma unroll
        for (int r = 0; r < 4; r++) o[nt][r] = 0.f;

    const uint32_t vaddr = Vs + (lane & 15) * 144 + (lane >> 4) * 16;
    #pragma unroll
    for (int kc = 0; kc < 16; kc++) {
        #pragma unroll
        for (int ngi = 0; ngi < 4; ngi++) {
            uint32_t bb[4];
            LDMATRIX_X4_TRANS(bb[0], bb[1], bb[2], bb[3],
                              vaddr + kc * 2304 + ngi * 32);
            MMA_F16(o[2 * ngi],     aP[kc], bb[0], bb[1]);
            MMA_F16(o[2 * ngi + 1], aP[kc], bb[2], bb[3]);
        }
    }

    __nv_bfloat16* og = g_ao_bf + ((long)(b * 2048 + cc * 64 + wid * 16)) * 1024 + hh * 64;
    #pragma unroll
    for (int nt = 0; nt < 8; nt++) {
        const int col = nt * 8 + tig * 2;
        *reinterpret_cast<__nv_bfloat162*>(og + (long)g * 1024 + col) =
            __floats2bfloat162_rn(o[nt][0] * inv0, o[nt][1] * inv0);
        *reinterpret_cast<__nv_bfloat162*>(og + (long)(g + 8) * 1024 + col) =
            __floats2bfloat162_rn(o[nt][2] * inv1, o[nt][3] * inv1);
    }
}

// ---------------------------------------------------------------------------
extern "C" void kernel_launch(void* const* d_in, const int* in_sizes, int n_in,
                              void* d_out, int out_size) {
    (void)in_sizes; (void)n_in; (void)out_size;
    const float* h     = (const float*)d_in[0];
    const float* e     = (const float*)d_in[1];
    const float* Wq    = (const float*)d_in[2];
    const float* bq    = (const float*)d_in[3];
    const float* Wk    = (const float*)d_in[4];
    const float* bk    = (const float*)d_in[5];
    const float* Wv    = (const float*)d_in[6];
    const float* bv    = (const float*)d_in[7];
    const float* Wo    = (const float*)d_in[8];
    const float* bo    = (const float*)d_in[9];
    const float* gamma = (const float*)d_in[10];
    const float* beta  = (const float*)d_in[11];
    float* out = (float*)d_out;

    void *p_hsn, *p_e, *p_ao, *p_wT, *p_q, *p_k, *p_v;
    cudaGetSymbolAddress(&p_hsn, g_hsn_bf);
    cudaGetSymbolAddress(&p_e,   g_e_bf);
    cudaGetSymbolAddress(&p_ao,  g_ao_bf);
    cudaGetSymbolAddress(&p_wT,  g_wT_bf);
    cudaGetSymbolAddress(&p_q,   g_q_h);
    cudaGetSymbolAddress(&p_k,   g_k_h);
    cudaGetSymbolAddress(&p_v,   g_v_h);
    __nv_bfloat16* wT = (__nv_bfloat16*)p_wT;
    __nv_bfloat16* wTo = wT + 3 * 1024 * 1024;

    cudaFuncSetAttribute(attn_kernel, cudaFuncAttributeMaxDynamicSharedMemorySize,
                         AT_SMEM);
    cudaFuncSetAttribute(qkv_gemm, cudaFuncAttributeMaxDynamicSharedMemorySize,
                         GM_SMEM);
    cudaFuncSetAttribute(o_gemm, cudaFuncAttributeMaxDynamicSharedMemorySize,
                         GM_SMEM);

    // 1. LayerNorm -> bf16
    ln_kernel<<<4 * 2048, 256>>>(h, gamma, beta);
    // 2. e -> bf16
    cvt_e<<<16384, 256>>>(e);
    // 3. Weight transposes -> bf16 (single launch)
    transpose_w4<<<dim3(32, 32, 4), dim3(32, 8)>>>(Wq, Wk, Wv, Wo, wT);
    // 4. Q+K+V projections, one launch (fp16 out)
    qkv_gemm<<<dim3(8, 576), 256, GM_SMEM>>>(
        (const __nv_bfloat16*)p_hsn, (const __nv_bfloat16*)p_e, wT,
        bq, bk, bv, (__half*)p_q, (__half*)p_k, (__half*)p_v);
    // 5. Flash attention (fp16 tensor cores)
    attn_kernel<<<dim3(16, 32, 4), 128, AT_SMEM>>>();
    // 6. Output projection + shift + bias + residual
    o_gemm<<<dim3(8, 64), 256, GM_SMEM>>>(
        (const __nv_bfloat16*)p_ao, wTo, bo, h, out);
}